// round 4
// baseline (speedup 1.0000x reference)
#include <cuda_runtime.h>
#include <cstdint>

#define L_SEQ 1024
#define N_ST  256

// Output layout: concat of (c_all[L,N], y_all[L], GBT_A[L,N,N], GBT_B[L,N])
#define OFF_C  ((size_t)0)
#define OFF_Y  ((size_t)(L_SEQ * N_ST))
#define OFF_A  (OFF_Y + (size_t)L_SEQ)
#define OFF_B  (OFF_A + (size_t)L_SEQ * N_ST * N_ST)

// fillA coefficients: [k][0][j] = a_j = s*r_j/e_j,  [k][1][j] = 1/e_j   (2MB)
__device__ float g_tab[L_SEQ][2][N_ST];
// scan coefficients, packed per stage (stage = 2 states):
// [k][st] = {G0, G1, H0, H1, b0, b1, pad, pad}                         (4MB)
__device__ float s_tab[L_SEQ][128][8];

// ---------------------------------------------------------------------------
__device__ __forceinline__ unsigned ld_acq_cta(const unsigned* p) {
    unsigned v;
    asm volatile("ld.acquire.cta.u32 %0, [%1];" : "=r"(v) : "l"(p) : "memory");
    return v;
}
__device__ __forceinline__ void st_rel_cta(unsigned* p, unsigned v) {
    asm volatile("st.release.cta.u32 [%0], %1;" :: "l"(p), "r"(v) : "memory");
}

// ---------------------------------------------------------------------------
// Tables + GBT_B.  Bd_j = ss*(r_j/e_j)*prod_{l<j}(1 - s*r_l^2/e_l).
// ---------------------------------------------------------------------------
__global__ void __launch_bounds__(N_ST) hippo_tabs(
        const float* __restrict__ f, const float* __restrict__ Bvec,
        float* __restrict__ out) {
    __shared__ float sc[2][N_ST];
    const int k = blockIdx.x, j = threadIdx.x;
    const float ss = 1.0f / (float)(k + 1);
    const float s  = 0.5f * ss;
    const float r  = Bvec[j];
    const float e  = fmaf(s, (float)(j + 1), 1.0f);
    const float h  = 1.0f / e;
    const float g  = s * r * h;
    const float al = fmaf(-r, g, 1.0f);

    int pb = 0;
    sc[0][j] = al;
    __syncthreads();
    #pragma unroll
    for (int off = 1; off < N_ST; off <<= 1) {
        float v = sc[pb][j];
        if (j >= off) v *= sc[pb][j - off];
        sc[pb ^ 1][j] = v;
        pb ^= 1;
        __syncthreads();
    }
    const float E  = (j == 0) ? 1.0f : sc[pb][j - 1];
    const float Bd = ss * r * h * E;

    g_tab[k][0][j] = g;
    g_tab[k][1][j] = h;
    out[OFF_B + (size_t)k * N_ST + j] = Bd;

    const int st = j >> 1, sl = j & 1;
    s_tab[k][st][0 + sl] = g;
    s_tab[k][st][2 + sl] = h;
    s_tab[k][st][4 + sl] = Bd * f[k];
}

// ---------------------------------------------------------------------------
// Barrier-free systolic scan: 128 stages (= threads), 2 states/stage.
// Stage g processes step k at tick t = k + d(g), d(g) = 40*warp + lane.
// In-warp handoff: shfl.up.  Cross-warp: full-length smem FIFO + release/
// acquire counter published every 8 steps (consumer has 9 ticks of slack,
// so the acquire poll virtually never spins).
// ---------------------------------------------------------------------------
#define WDELAY 40
#define TICKS  1176   // >= 1024 + 3*40 + 31; multiple of 8

__global__ void __launch_bounds__(128) hippo_scan(
        const float* __restrict__ initS, const float* __restrict__ Bvec,
        float* __restrict__ out) {
    __shared__ float2   fifo[3][L_SEQ];   // 24KB
    __shared__ unsigned cnt[3];

    const int g    = threadIdx.x;
    const int w    = g >> 5;
    const int lane = g & 31;
    const int i0   = 2 * g;
    const int d    = w * WDELAY + lane;

    if (g < 3) cnt[g] = 0;
    __syncthreads();                       // one-time init only

    const float r0 = Bvec[i0], r1 = Bvec[i0 + 1];
    float c0 = initS[i0], c1 = initS[i0 + 1];

    float* outC = out + OFF_C;
    float* outY = out + OFF_Y;

    // Depth-8 register prefetch ring: 2 x LDG.128 per tick.
    float4 pf[8][2];
    auto pref = [&](int slot, int t) {
        int kk = t - d;
        kk = (kk < 0) ? 0 : (kk > L_SEQ - 1 ? L_SEQ - 1 : kk);
        const float4* p = (const float4*)&s_tab[kk][g][0];
        pf[slot][0] = p[0];
        pf[slot][1] = p[1];
    };
    #pragma unroll
    for (int u = 0; u < 8; u++) pref(u, u);

    float V = 0.0f, ys = 0.0f;
    unsigned avail = 0;

    for (int t0 = 0; t0 < TICKS; t0 += 8) {
        #pragma unroll
        for (int u = 0; u < 8; u++) {
            const int t = t0 + u;
            float Vin = __shfl_up_sync(0xffffffffu, V, 1);
            float yin = __shfl_up_sync(0xffffffffu, ys, 1);
            const int k = t - d;
            if (lane == 0) {
                Vin = 0.0f; yin = 0.0f;
                if (w > 0 && (unsigned)k < (unsigned)L_SEQ) {
                    while ((int)avail <= k) avail = ld_acq_cta(&cnt[w - 1]);
                    float2 m = fifo[w - 1][k];
                    Vin = m.x; yin = m.y;
                }
            }
            if ((unsigned)k < (unsigned)L_SEQ) {
                const float G0 = pf[u][0].x, G1 = pf[u][0].y;
                const float H0 = pf[u][0].z, H1 = pf[u][0].w;
                const float b0 = pf[u][1].x, b1 = pf[u][1].y;

                V = Vin;
                const float hc0 = H0 * c0;
                const float z0  = fmaf(-G0, V, hc0);
                const float al0 = fmaf(-r0, G0, 1.0f);
                V = fmaf(al0, V, r0 * hc0);
                const float cn0 = fmaf(2.0f, z0, b0 - c0);

                const float hc1 = H1 * c1;
                const float z1  = fmaf(-G1, V, hc1);
                const float al1 = fmaf(-r1, G1, 1.0f);
                V = fmaf(al1, V, r1 * hc1);
                const float cn1 = fmaf(2.0f, z1, b1 - c1);

                ys = yin + (cn0 + cn1);
                c0 = cn0; c1 = cn1;

                *(float2*)(outC + (size_t)k * N_ST + i0) = make_float2(cn0, cn1);
                if (g == 127) outY[k] = ys;

                if (lane == 31 && w < 3) {
                    fifo[w][k] = make_float2(V, ys);
                    if ((k & 7) == 7 || k == L_SEQ - 1)
                        st_rel_cta(&cnt[w], (unsigned)(k + 1));
                }
            } else {
                V = 0.0f; ys = 0.0f;
            }
            pref(u, t + 8);
        }
    }
}

// ---------------------------------------------------------------------------
// GBT_A fill (Round-1 proven shape): thread j owns column j of Ad = 2M - I,
// M = P1^{-1} by forward substitution; 1KB coalesced row stores.
// ---------------------------------------------------------------------------
__global__ void __launch_bounds__(N_ST) hippo_fillA(
        const float* __restrict__ Bvec, float* __restrict__ out) {
    __shared__ float r_s[N_ST], a_s[N_ST];
    const int k = blockIdx.x;
    const int j = threadIdx.x;

    r_s[j] = Bvec[j];
    a_s[j] = g_tab[k][0][j];
    const float rj = r_s[j];
    const float h  = g_tab[k][1][j];     // 1/e_j
    __syncthreads();

    float* outA = out + OFF_A + (size_t)k * (N_ST * N_ST) + j;
    float x = 0.0f, S = 0.0f;
    #pragma unroll 4
    for (int i = 0; i < N_ST; i++) {
        float val;
        if (i < j) {
            val = 0.0f;
        } else if (i == j) {
            x = h; S = rj * x;
            val = fmaf(2.0f, x, -1.0f);
        } else {
            x = -a_s[i] * S;
            S = fmaf(r_s[i], x, S);
            val = 2.0f * x;
        }
        outA[(size_t)i * N_ST] = val;
    }
}

// ---------------------------------------------------------------------------
extern "C" void kernel_launch(void* const* d_in, const int* in_sizes, int n_in,
                              void* d_out, int out_size) {
    const float* f    = (const float*)d_in[0];  // (L,1)
    const float* init = (const float*)d_in[1];  // (N,1)
    // d_in[2] = A (unused: closed form), d_in[3] = B (= r vector)
    const float* B    = (const float*)d_in[3];
    float* out = (float*)d_out;

    hippo_tabs <<<L_SEQ, N_ST>>>(f, B, out);
    hippo_scan <<<1, 128>>>(init, B, out);      // runs on L2-hot s_tab
    hippo_fillA<<<L_SEQ, N_ST>>>(B, out);
}

// round 5
// speedup vs baseline: 4.9836x; 4.9836x over previous
#include <cuda_runtime.h>
#include <cstdint>

#define L_SEQ 1024
#define N_ST  256

// Output layout: concat of (c_all[L,N], y_all[L], GBT_A[L,N,N], GBT_B[L,N])
#define OFF_C  ((size_t)0)
#define OFF_Y  ((size_t)(L_SEQ * N_ST))
#define OFF_A  (OFF_Y + (size_t)L_SEQ)
#define OFF_B  (OFF_A + (size_t)L_SEQ * N_ST * N_ST)

// fillA coefficients: [k][0][j] = a_j = s*r_j/e_j, [k][1][j] = 1/e_j   (2MB)
__device__ float g_tab[L_SEQ][2][N_ST];
// scan coefficients, 64 stages x 4 states, 20 floats per (k,stage):
// {P0..P3, Q0..Q3, al0..al3, R0..R3, b0..b3}
//   P = 2h-1, Q = 2g, al = 1-r*g, R = r*h, b = Bd*f_k            (5.2MB)
__device__ float st_tab[L_SEQ][64][20];

// ---------------------------------------------------------------------------
// Tables + GBT_B.  Bd_j = ss*(r_j/e_j)*prod_{l<j}(1 - s*r_l^2/e_l).
// ---------------------------------------------------------------------------
__global__ void __launch_bounds__(N_ST) hippo_tabs(
        const float* __restrict__ f, const float* __restrict__ Bvec,
        float* __restrict__ out) {
    __shared__ float sc[2][N_ST];
    const int k = blockIdx.x, j = threadIdx.x;
    const float ss = 1.0f / (float)(k + 1);
    const float s  = 0.5f * ss;
    const float r  = Bvec[j];
    const float e  = fmaf(s, (float)(j + 1), 1.0f);
    const float h  = 1.0f / e;
    const float g  = s * r * h;
    const float al = fmaf(-r, g, 1.0f);

    int pb = 0;
    sc[0][j] = al;
    __syncthreads();
    #pragma unroll
    for (int off = 1; off < N_ST; off <<= 1) {
        float v = sc[pb][j];
        if (j >= off) v *= sc[pb][j - off];
        sc[pb ^ 1][j] = v;
        pb ^= 1;
        __syncthreads();
    }
    const float E  = (j == 0) ? 1.0f : sc[pb][j - 1];
    const float Bd = ss * r * h * E;

    g_tab[k][0][j] = g;
    g_tab[k][1][j] = h;
    out[OFF_B + (size_t)k * N_ST + j] = Bd;

    const int stg = j >> 2, e4 = j & 3;
    float* T = &st_tab[k][stg][0];
    T[ 0 + e4] = fmaf(2.0f, h, -1.0f);   // P
    T[ 4 + e4] = 2.0f * g;               // Q
    T[ 8 + e4] = al;                     // al
    T[12 + e4] = r * h;                  // R
    T[16 + e4] = Bd * f[k];              // b
}

// ---------------------------------------------------------------------------
// Epoch-barrier systolic scan: 2 warps, 64 stages, 4 states/stage.
// Stage s processes step k at tick t = k + d(s), d = 63*warp + lane.
// In-warp handoff of V: shfl.up.  Cross-warp: plain smem fifo; warp 1 runs
// 63 ticks behind, and __syncthreads every 32 ticks guarantees every fifo
// entry it reads was written >= 32 ticks (>= 1 barrier) earlier.
// Per state:  t1 = fma(-Q,V,b); cn = fma(P,c,t1); V = fma(al,V,R*c).
// ---------------------------------------------------------------------------
#define WD      63
#define EPOCHS  35           // 35*32 = 1120 >= 1023 + 63 + 31 + 1
__global__ void __launch_bounds__(64) hippo_scan(
        const float* __restrict__ initS, float* __restrict__ out) {
    __shared__ float fifo[L_SEQ];        // 4KB

    const int s    = threadIdx.x;        // stage
    const int w    = s >> 5;
    const int lane = s & 31;
    const int i0   = 4 * s;
    const int d    = w * WD + lane;

    float c0 = initS[i0 + 0], c1 = initS[i0 + 1];
    float c2 = initS[i0 + 2], c3 = initS[i0 + 3];

    float* outC = out + OFF_C;

    // Depth-4 register prefetch ring: 5 x LDG.128 per tick.
    float4 pf[4][5];
    auto pref = [&](int slot, int t) {
        int kk = t - d;
        kk = (kk < 0) ? 0 : (kk > L_SEQ - 1 ? L_SEQ - 1 : kk);
        const float4* p = (const float4*)&st_tab[kk][s][0];
        pf[slot][0] = p[0];
        pf[slot][1] = p[1];
        pf[slot][2] = p[2];
        pf[slot][3] = p[3];
        pf[slot][4] = p[4];
    };
    #pragma unroll
    for (int u = 0; u < 4; u++) pref(u, u);

    float V = 0.0f;
    int t = 0;

    for (int ep = 0; ep < EPOCHS; ep++) {
        for (int q = 0; q < 8; q++) {
            #pragma unroll
            for (int u = 0; u < 4; u++) {
                float Vin = __shfl_up_sync(0xffffffffu, V, 1);
                const int k = t - d;
                const bool valid = ((unsigned)k < (unsigned)L_SEQ);
                if (lane == 0) Vin = (w == 1 && valid) ? fifo[k] : 0.0f;
                if (valid) {
                    const float4 P = pf[u][0], Q = pf[u][1];
                    const float4 A = pf[u][2], R = pf[u][3], B = pf[u][4];
                    V = Vin;
                    float t1, cn0, cn1, cn2, cn3;
                    t1  = fmaf(-Q.x, V, B.x);
                    cn0 = fmaf(P.x, c0, t1);
                    V   = fmaf(A.x, V, R.x * c0);
                    t1  = fmaf(-Q.y, V, B.y);
                    cn1 = fmaf(P.y, c1, t1);
                    V   = fmaf(A.y, V, R.y * c1);
                    t1  = fmaf(-Q.z, V, B.z);
                    cn2 = fmaf(P.z, c2, t1);
                    V   = fmaf(A.z, V, R.z * c2);
                    t1  = fmaf(-Q.w, V, B.w);
                    cn3 = fmaf(P.w, c3, t1);
                    V   = fmaf(A.w, V, R.w * c3);
                    c0 = cn0; c1 = cn1; c2 = cn2; c3 = cn3;
                    *(float4*)(outC + (size_t)k * N_ST + i0) =
                        make_float4(cn0, cn1, cn2, cn3);
                    if (s == 31) fifo[k] = V;   // boundary stage -> warp 1
                } else {
                    V = 0.0f;
                }
                pref(u, t + 4);
                t++;
            }
        }
        __syncthreads();                  // publish fifo once per 32 ticks
    }
}

// ---------------------------------------------------------------------------
// GBT_A fill (proven R1 shape) + y_all reduction fused in (c_all is ready).
// Thread j owns column j of Ad = 2M - I; 1KB coalesced row stores.
// ---------------------------------------------------------------------------
__global__ void __launch_bounds__(N_ST) hippo_fillA(
        const float* __restrict__ Bvec, float* __restrict__ out) {
    __shared__ float r_s[N_ST], a_s[N_ST];
    __shared__ float red[8];
    const int k = blockIdx.x;
    const int j = threadIdx.x;

    const float rj = Bvec[j];
    r_s[j] = rj;
    a_s[j] = g_tab[k][0][j];
    const float h = g_tab[k][1][j];      // 1/e_j
    __syncthreads();

    float* outA = out + OFF_A + (size_t)k * (N_ST * N_ST) + j;
    float x = 0.0f, S = 0.0f;
    #pragma unroll 4
    for (int i = 0; i < N_ST; i++) {
        float val;
        if (i < j) {
            val = 0.0f;
        } else if (i == j) {
            x = h; S = rj * x;
            val = fmaf(2.0f, x, -1.0f);
        } else {
            x = -a_s[i] * S;
            S = fmaf(r_s[i], x, S);
            val = 2.0f * x;
        }
        outA[(size_t)i * N_ST] = val;
    }

    // y_k = sum_j c_all[k][j]  (c_all written by hippo_scan, prior launch)
    float v = out[OFF_C + (size_t)k * N_ST + j];
    #pragma unroll
    for (int off = 16; off > 0; off >>= 1)
        v += __shfl_down_sync(0xffffffffu, v, off);
    if ((j & 31) == 0) red[j >> 5] = v;
    __syncthreads();
    if (j == 0) {
        float y = red[0] + red[1] + red[2] + red[3]
                + red[4] + red[5] + red[6] + red[7];
        out[OFF_Y + k] = y;
    }
}

// ---------------------------------------------------------------------------
extern "C" void kernel_launch(void* const* d_in, const int* in_sizes, int n_in,
                              void* d_out, int out_size) {
    const float* f    = (const float*)d_in[0];  // (L,1)
    const float* init = (const float*)d_in[1];  // (N,1)
    // d_in[2] = A (unused: closed form), d_in[3] = B (= r vector)
    const float* B    = (const float*)d_in[3];
    float* out = (float*)d_out;

    hippo_tabs <<<L_SEQ, N_ST>>>(f, B, out);
    hippo_scan <<<1, 64>>>(init, out);
    hippo_fillA<<<L_SEQ, N_ST>>>(B, out);
}